// round 4
// baseline (speedup 1.0000x reference)
#include <cuda_runtime.h>
#include <math.h>

#define DIM     256
#define BATCH   4
#define NODES   2048
#define MAXDEG  64
#define POOLMAX 1024

// ---------------- persistent device scratch -----------------------------------
__device__ float  g_h [BATCH*NODES*DIM];
__device__ float  g_h2[BATCH*NODES*DIM];
__device__ float  g_hn[BATCH*NODES*DIM];
__device__ float  g_t [BATCH*NODES*DIM];
__device__ float  g_pe[NODES*DIM];
__device__ float2 g_stats[BATCH*NODES];   // per-row mean, rstd
__device__ float  g_score[BATCH*NODES];
__device__ float  g_gate [BATCH*POOLMAX];
__device__ float  g_posstat[8];
__device__ float  g_pnorm[4];
__device__ int    g_idx[BATCH*POOLMAX];
__device__ int    g_map[BATCH*NODES];
__device__ int    g_cols0[NODES*MAXDEG];
__device__ int    g_cnt0 [NODES];
__device__ int    g_colsA[BATCH*POOLMAX*MAXDEG];
__device__ int    g_cntA [BATCH*POOLMAX];
__device__ int    g_colsB[BATCH*POOLMAX*MAXDEG];
__device__ int    g_cntB [BATCH*POOLMAX];

// ---------------- f32x2 packed-FMA helpers (sm_10x) ---------------------------
__device__ __forceinline__ unsigned long long pack2s(float x) {
    unsigned long long r;
    asm("mov.b64 %0, {%1, %1};" : "=l"(r) : "f"(x));
    return r;
}
__device__ __forceinline__ unsigned long long pack2(float x, float y) {
    unsigned long long r;
    asm("mov.b64 %0, {%1, %2};" : "=l"(r) : "f"(x), "f"(y));
    return r;
}
__device__ __forceinline__ void ffma2(unsigned long long &d, unsigned long long a,
                                      unsigned long long b) {
    asm("fma.rn.f32x2 %0, %1, %2, %3;" : "=l"(d) : "l"(a), "l"(b), "l"(d));
}
__device__ __forceinline__ void unpack2(unsigned long long v, float &lo, float &hi) {
    asm("mov.b64 {%0, %1}, %2;" : "=f"(lo), "=f"(hi) : "l"(v));
}

// ---------------------------- prologue kernels --------------------------------

// pos column stats + pool-projection inverse norms, one kernel
__global__ void stats_prologue_kernel(const float* __restrict__ pos,
                                      const float* __restrict__ pp) {
    __shared__ float red[256];
    __shared__ float smean;
    int t = threadIdx.x;
    for (int c = 0; c < 3; c++) {
        float s = 0.f;
        for (int i = t; i < NODES; i += 256) s += pos[i*3 + c];
        red[t] = s; __syncthreads();
        for (int o = 128; o > 0; o >>= 1) { if (t < o) red[t] += red[t+o]; __syncthreads(); }
        if (t == 0) smean = red[0] / (float)NODES;
        __syncthreads();
        float m = smean;
        float ss = 0.f;
        for (int i = t; i < NODES; i += 256) { float d = pos[i*3 + c] - m; ss += d*d; }
        red[t] = ss; __syncthreads();
        for (int o = 128; o > 0; o >>= 1) { if (t < o) red[t] += red[t+o]; __syncthreads(); }
        if (t == 0) {
            float var = (float)BATCH * red[0] / (float)(BATCH*NODES - 1);
            g_posstat[c]   = m;
            g_posstat[3+c] = 1.f / (sqrtf(var) + 1e-8f);
        }
        __syncthreads();
    }
    for (int dep = 0; dep < 3; dep++) {
        float v = pp[dep*DIM + t];
        red[t] = v*v; __syncthreads();
        for (int o = 128; o > 0; o >>= 1) { if (t < o) red[t] += red[t+o]; __syncthreads(); }
        if (t == 0) g_pnorm[dep] = 1.f / sqrtf(red[0]);
        __syncthreads();
    }
}

__global__ void pos_mid_kernel(const float* __restrict__ pos,
                               const float* __restrict__ pw1,
                               const float* __restrict__ pb1) {
    int i = blockIdx.x, d = threadIdx.x;
    __shared__ float pn[3];
    if (d < 3) pn[d] = (pos[i*3 + d] - g_posstat[d]) * g_posstat[3+d];
    __syncthreads();
    float a = pb1[d] + pn[0]*pw1[d] + pn[1]*pw1[DIM + d] + pn[2]*pw1[2*DIM + d];
    g_hn[i*DIM + d] = a / (1.f + __expf(-a));
}

__global__ void embed_kernel(const float* __restrict__ x,
                             const float* __restrict__ in_w,
                             const float* __restrict__ in_b) {
    int r = blockIdx.x, d = threadIdx.x;
    __shared__ float xr[16];
    if (d < 16) xr[d] = x[r*16 + d];
    __syncthreads();
    float a = in_b[d] + g_pe[(r & (NODES-1))*DIM + d];
#pragma unroll
    for (int k = 0; k < 16; k++) a += xr[k]*in_w[k*DIM + d];
    g_h[(size_t)r*DIM + d] = a;
}

__global__ void build_csr_kernel(const float* __restrict__ adj) {
    int warp = (blockIdx.x*blockDim.x + threadIdx.x) >> 5;
    int lane = threadIdx.x & 31;
    if (warp >= NODES) return;
    int base = 0;
    for (int it = 0; it < NODES/32; it++) {
        int col = it*32 + lane;
        float v = adj[(size_t)warp*NODES + col];
        unsigned m = __ballot_sync(0xffffffffu, v > 0.f);
        if (v > 0.f) {
            int p = base + __popc(m & ((1u << lane) - 1u));
            if (p < MAXDEG) g_cols0[warp*MAXDEG + p] = col;
        }
        base += __popc(m);
    }
    if (lane == 0) g_cnt0[warp] = base < MAXDEG ? base : MAXDEG;
}

// per-row mean / rstd (LN applied later inline in combine). one warp per row.
__global__ void rowstats_kernel(const float* __restrict__ H, int rows) {
    int warp = (blockIdx.x*blockDim.x + threadIdx.x) >> 5;
    int lane = threadIdx.x & 31;
    if (warp >= rows) return;
    const float* hr = H + (size_t)warp*DIM;
    float v[8]; float s = 0.f;
#pragma unroll
    for (int q = 0; q < 8; q++) { v[q] = hr[lane + 32*q]; s += v[q]; }
#pragma unroll
    for (int o = 16; o; o >>= 1) s += __shfl_xor_sync(0xffffffffu, s, o);
    float m = s * (1.f/DIM);
    float vs = 0.f;
#pragma unroll
    for (int q = 0; q < 8; q++) { float d = v[q] - m; vs += d*d; }
#pragma unroll
    for (int o = 16; o; o >>= 1) vs += __shfl_xor_sync(0xffffffffu, vs, o);
    if (lane == 0) {
        float rstd = rsqrtf(vs * (1.f/DIM) + 1e-5f);
        g_stats[warp] = make_float2(m, rstd);
    }
}

// t_i = (1+eps)*LN(h_i) + sum_j LN(h_j), LN applied inline via g_stats
__global__ void combine_kernel(const float* __restrict__ H, int n, int adjSel,
                               const float* __restrict__ beps, int blk,
                               const float* __restrict__ gam,
                               const float* __restrict__ bet) {
    int b = blockIdx.x / n, i = blockIdx.x % n, d = threadIdx.x;
    const int* cols; const int* cnt; int rowbase;
    if (adjSel == 0)      { cols = g_cols0; cnt = g_cnt0; rowbase = i; }
    else if (adjSel == 1) { cols = g_colsA; cnt = g_cntA; rowbase = b*POOLMAX + i; }
    else                  { cols = g_colsB; cnt = g_cntB; rowbase = b*POOLMAX + i; }
    __shared__ int cs[MAXDEG];
    int c = cnt[rowbase];
    if (d < c) cs[d] = cols[rowbase*MAXDEG + d];
    __syncthreads();
    float eps = beps[blk];
    float gd = gam[d], bd = bet[d];
    const float* hb = H + (size_t)b*n*DIM;
    const float2* st = g_stats + b*n;
    float2 si = st[i];
    float acc = (1.f + eps)*((hb[(size_t)i*DIM + d] - si.x)*si.y*gd + bd);
    for (int q = 0; q < c; q++) {
        int j = cs[q];
        float2 sj = st[j];
        acc += (hb[(size_t)j*DIM + d] - sj.x)*sj.y*gd + bd;
    }
    g_t[((size_t)b*n + i)*DIM + d] = acc;
}

// ------------- SGEMM big: 128x64 tile, 128 thr, 8x8/thread, BK=16 -------------
// mode 0: C=acc+bias ; 1: silu ; 2: res+acc+bias
__global__ __launch_bounds__(128, 4)
void sgemm_big(const float* __restrict__ A, const float* __restrict__ Bw,
               const float* __restrict__ bias, const float* __restrict__ res,
               float* __restrict__ C, int mode) {
    __shared__ float As[2][16][128];
    __shared__ float Bs[2][16][64];
    int t  = threadIdx.x;
    int bm = blockIdx.y, bn = blockIdx.x;
    int ty = t >> 3, tx = t & 7;
    int brow = t >> 3, bcol = (t & 7)*8;
    const float* Ap = A  + (size_t)(bm*128 + t)*DIM;
    const float* Bp = Bw + (size_t)brow*DIM + bn*64 + bcol;

    unsigned long long acc[8][4];
#pragma unroll
    for (int i = 0; i < 8; i++)
#pragma unroll
        for (int j = 0; j < 4; j++) acc[i][j] = 0ull;

    float4 a0 = *(const float4*)(Ap);
    float4 a1 = *(const float4*)(Ap + 4);
    float4 a2 = *(const float4*)(Ap + 8);
    float4 a3 = *(const float4*)(Ap + 12);
    float4 b0 = *(const float4*)(Bp);
    float4 b1 = *(const float4*)(Bp + 4);
    As[0][ 0][t] = a0.x; As[0][ 1][t] = a0.y; As[0][ 2][t] = a0.z; As[0][ 3][t] = a0.w;
    As[0][ 4][t] = a1.x; As[0][ 5][t] = a1.y; As[0][ 6][t] = a1.z; As[0][ 7][t] = a1.w;
    As[0][ 8][t] = a2.x; As[0][ 9][t] = a2.y; As[0][10][t] = a2.z; As[0][11][t] = a2.w;
    As[0][12][t] = a3.x; As[0][13][t] = a3.y; As[0][14][t] = a3.z; As[0][15][t] = a3.w;
    *(float4*)&Bs[0][brow][bcol]     = b0;
    *(float4*)&Bs[0][brow][bcol + 4] = b1;
    __syncthreads();

    int cur = 0;
    for (int k0 = 16; k0 < DIM; k0 += 16) {
        a0 = *(const float4*)(Ap + k0);
        a1 = *(const float4*)(Ap + k0 + 4);
        a2 = *(const float4*)(Ap + k0 + 8);
        a3 = *(const float4*)(Ap + k0 + 12);
        b0 = *(const float4*)(Bp + (size_t)k0*DIM);
        b1 = *(const float4*)(Bp + (size_t)k0*DIM + 4);
#pragma unroll
        for (int kk = 0; kk < 16; kk++) {
            float4 aA = *(const float4*)&As[cur][kk][ty*8];
            float4 aB = *(const float4*)&As[cur][kk][ty*8 + 4];
            float4 bA = *(const float4*)&Bs[cur][kk][tx*8];
            float4 bB = *(const float4*)&Bs[cur][kk][tx*8 + 4];
            unsigned long long bp[4] = { pack2(bA.x, bA.y), pack2(bA.z, bA.w),
                                         pack2(bB.x, bB.y), pack2(bB.z, bB.w) };
            float am[8] = { aA.x, aA.y, aA.z, aA.w, aB.x, aB.y, aB.z, aB.w };
#pragma unroll
            for (int i = 0; i < 8; i++) {
                unsigned long long ap = pack2s(am[i]);
#pragma unroll
                for (int j = 0; j < 4; j++) ffma2(acc[i][j], ap, bp[j]);
            }
        }
        int nxt = cur ^ 1;
        As[nxt][ 0][t] = a0.x; As[nxt][ 1][t] = a0.y; As[nxt][ 2][t] = a0.z; As[nxt][ 3][t] = a0.w;
        As[nxt][ 4][t] = a1.x; As[nxt][ 5][t] = a1.y; As[nxt][ 6][t] = a1.z; As[nxt][ 7][t] = a1.w;
        As[nxt][ 8][t] = a2.x; As[nxt][ 9][t] = a2.y; As[nxt][10][t] = a2.z; As[nxt][11][t] = a2.w;
        As[nxt][12][t] = a3.x; As[nxt][13][t] = a3.y; As[nxt][14][t] = a3.z; As[nxt][15][t] = a3.w;
        *(float4*)&Bs[nxt][brow][bcol]     = b0;
        *(float4*)&Bs[nxt][brow][bcol + 4] = b1;
        __syncthreads();
        cur = nxt;
    }
#pragma unroll
    for (int kk = 0; kk < 16; kk++) {
        float4 aA = *(const float4*)&As[cur][kk][ty*8];
        float4 aB = *(const float4*)&As[cur][kk][ty*8 + 4];
        float4 bA = *(const float4*)&Bs[cur][kk][tx*8];
        float4 bB = *(const float4*)&Bs[cur][kk][tx*8 + 4];
        unsigned long long bp[4] = { pack2(bA.x, bA.y), pack2(bA.z, bA.w),
                                     pack2(bB.x, bB.y), pack2(bB.z, bB.w) };
        float am[8] = { aA.x, aA.y, aA.z, aA.w, aB.x, aB.y, aB.z, aB.w };
#pragma unroll
        for (int i = 0; i < 8; i++) {
            unsigned long long ap = pack2s(am[i]);
#pragma unroll
            for (int j = 0; j < 4; j++) ffma2(acc[i][j], ap, bp[j]);
        }
    }

#pragma unroll
    for (int i = 0; i < 8; i++) {
        int rg = bm*128 + ty*8 + i;
#pragma unroll
        for (int j = 0; j < 4; j++) {
            int cg = bn*64 + tx*8 + j*2;
            float lo, hi;
            unpack2(acc[i][j], lo, hi);
            float v0 = lo + bias[cg];
            float v1 = hi + bias[cg + 1];
            if (mode == 1) {
                v0 = v0 / (1.f + __expf(-v0));
                v1 = v1 / (1.f + __expf(-v1));
            } else if (mode == 2) {
                v0 = res[(size_t)rg*DIM + cg]     + v0;
                v1 = res[(size_t)rg*DIM + cg + 1] + v1;
            }
            C[(size_t)rg*DIM + cg]     = v0;
            C[(size_t)rg*DIM + cg + 1] = v1;
        }
    }
}

// ------------- SGEMM small: 32x64 tile, 128 thr, 2x8/thread, BK=16 ------------
__global__ __launch_bounds__(128, 8)
void sgemm_small(const float* __restrict__ A, const float* __restrict__ Bw,
                 const float* __restrict__ bias, const float* __restrict__ res,
                 float* __restrict__ C, int mode) {
    __shared__ float As[2][16][32];
    __shared__ float Bs[2][16][64];
    int t  = threadIdx.x;
    int bm = blockIdx.y, bn = blockIdx.x;
    int ty = t >> 3, tx = t & 7;
    int arow = t >> 2, acol = (t & 3)*4;
    int brow = t >> 3, bcol = (t & 7)*8;
    const float* Ap = A  + (size_t)(bm*32 + arow)*DIM + acol;
    const float* Bp = Bw + (size_t)brow*DIM + bn*64 + bcol;

    unsigned long long acc[2][4];
#pragma unroll
    for (int i = 0; i < 2; i++)
#pragma unroll
        for (int j = 0; j < 4; j++) acc[i][j] = 0ull;

    float4 av = *(const float4*)(Ap);
    float4 b0 = *(const float4*)(Bp);
    float4 b1 = *(const float4*)(Bp + 4);
    As[0][acol+0][arow] = av.x; As[0][acol+1][arow] = av.y;
    As[0][acol+2][arow] = av.z; As[0][acol+3][arow] = av.w;
    *(float4*)&Bs[0][brow][bcol]     = b0;
    *(float4*)&Bs[0][brow][bcol + 4] = b1;
    __syncthreads();

    int cur = 0;
    for (int k0 = 16; k0 < DIM; k0 += 16) {
        av = *(const float4*)(Ap + k0);
        b0 = *(const float4*)(Bp + (size_t)k0*DIM);
        b1 = *(const float4*)(Bp + (size_t)k0*DIM + 4);
#pragma unroll
        for (int kk = 0; kk < 16; kk++) {
            float2 a2 = *(const float2*)&As[cur][kk][ty*2];
            float4 bA = *(const float4*)&Bs[cur][kk][tx*8];
            float4 bB = *(const float4*)&Bs[cur][kk][tx*8 + 4];
            unsigned long long bp[4] = { pack2(bA.x, bA.y), pack2(bA.z, bA.w),
                                         pack2(bB.x, bB.y), pack2(bB.z, bB.w) };
            unsigned long long ap0 = pack2s(a2.x), ap1 = pack2s(a2.y);
#pragma unroll
            for (int j = 0; j < 4; j++) { ffma2(acc[0][j], ap0, bp[j]); ffma2(acc[1][j], ap1, bp[j]); }
        }
        int nxt = cur ^ 1;
        As[nxt][acol+0][arow] = av.x; As[nxt][acol+1][arow] = av.y;
        As[nxt][acol+2][arow] = av.z; As[nxt][acol+3][arow] = av.w;
        *(float4*)&Bs[nxt][brow][bcol]     = b0;
        *(float4*)&Bs[nxt][brow][bcol + 4] = b1;
        __syncthreads();
        cur = nxt;
    }
#pragma unroll
    for (int kk = 0; kk < 16; kk++) {
        float2 a2 = *(const float2*)&As[cur][kk][ty*2];
        float4 bA = *(const float4*)&Bs[cur][kk][tx*8];
        float4 bB = *(const float4*)&Bs[cur][kk][tx*8 + 4];
        unsigned long long bp[4] = { pack2(bA.x, bA.y), pack2(bA.z, bA.w),
                                     pack2(bB.x, bB.y), pack2(bB.z, bB.w) };
        unsigned long long ap0 = pack2s(a2.x), ap1 = pack2s(a2.y);
#pragma unroll
        for (int j = 0; j < 4; j++) { ffma2(acc[0][j], ap0, bp[j]); ffma2(acc[1][j], ap1, bp[j]); }
    }

#pragma unroll
    for (int i = 0; i < 2; i++) {
        int rg = bm*32 + ty*2 + i;
#pragma unroll
        for (int j = 0; j < 4; j++) {
            int cg = bn*64 + tx*8 + j*2;
            float lo, hi;
            unpack2(acc[i][j], lo, hi);
            float v0 = lo + bias[cg];
            float v1 = hi + bias[cg + 1];
            if (mode == 1) {
                v0 = v0 / (1.f + __expf(-v0));
                v1 = v1 / (1.f + __expf(-v1));
            } else if (mode == 2) {
                v0 = res[(size_t)rg*DIM + cg]     + v0;
                v1 = res[(size_t)rg*DIM + cg + 1] + v1;
            }
            C[(size_t)rg*DIM + cg]     = v0;
            C[(size_t)rg*DIM + cg + 1] = v1;
        }
    }
}

static inline void launch_sgemm(const float* A, const float* Bw, const float* bias,
                                const float* res, float* C, int rows, int mode) {
    if (rows >= 4096) sgemm_big  <<<dim3(4, rows/128), 128>>>(A, Bw, bias, res, C, mode);
    else              sgemm_small<<<dim3(4, rows/32 ), 128>>>(A, Bw, bias, res, C, mode);
}

// ------------------------------ pooling ---------------------------------------
__global__ void score_kernel(const float* __restrict__ H, const float* __restrict__ p,
                             int dep, int rows) {
    int warp = (blockIdx.x*blockDim.x + threadIdx.x) >> 5;
    int lane = threadIdx.x & 31;
    if (warp >= rows) return;
    const float* hr = H + (size_t)warp*DIM;
    float s = 0.f;
#pragma unroll
    for (int q = 0; q < 8; q++) s += hr[lane + 32*q]*p[lane + 32*q];
#pragma unroll
    for (int o = 16; o; o >>= 1) s += __shfl_xor_sync(0xffffffffu, s, o);
    if (lane == 0) g_score[warp] = s * g_pnorm[dep];
}

// exact top-k (lax.top_k tie-break) + compaction + sub-adjacency, one kernel
__global__ void topk_subadj_kernel(int n, int k, int oldSel, int newSel) {
    __shared__ float s[NODES];
    __shared__ unsigned char sel[NODES];
    int b = blockIdx.x, t = threadIdx.x, bd = blockDim.x;
    const float* sb = g_score + b*n;
    for (int i = t; i < n; i += bd) s[i] = sb[i];
    __syncthreads();
    for (int i = t; i < n; i += bd) {
        float si = s[i]; int r = 0;
        for (int j = 0; j < n; j++) {
            float sj = s[j];
            r += (sj > si) || (sj == si && j < i);
        }
        sel[i] = (r < k) ? 1 : 0;
    }
    __syncthreads();
    for (int i = t; i < n; i += bd) {
        if (sel[i]) {
            int p = 0;
            for (int j = 0; j < i; j++) p += sel[j];
            g_idx [b*POOLMAX + p] = i;
            g_gate[b*POOLMAX + p] = tanhf(s[i]);
            g_map [b*NODES + i]   = p;
        } else {
            g_map[b*NODES + i] = -1;
        }
    }
    __syncthreads();
    // sub-adjacency for this batch's k kept rows
    for (int r = t; r < k; r += bd) {
        int i = g_idx[b*POOLMAX + r];
        const int* ocols; const int* ocnt; int obase;
        if (oldSel == 0)      { ocols = g_cols0; ocnt = g_cnt0; obase = i; }
        else if (oldSel == 1) { ocols = g_colsA; ocnt = g_cntA; obase = b*POOLMAX + i; }
        else                  { ocols = g_colsB; ocnt = g_cntB; obase = b*POOLMAX + i; }
        int* ncols = (newSel == 1) ? g_colsA : g_colsB;
        int* ncnt  = (newSel == 1) ? g_cntA  : g_cntB;
        int c = ocnt[obase], w = 0, nb = b*POOLMAX + r;
        for (int q = 0; q < c; q++) {
            int j  = ocols[obase*MAXDEG + q];
            int nj = g_map[b*NODES + j];
            if (nj >= 0) ncols[nb*MAXDEG + w++] = nj;
        }
        ncnt[nb] = w;
    }
}

__global__ void gather_kernel(const float* __restrict__ H, float* __restrict__ O,
                              int n, int k) {
    int b = blockIdx.x / k, r = blockIdx.x % k, d = threadIdx.x;
    int i  = g_idx [b*POOLMAX + r];
    float g = g_gate[b*POOLMAX + r];
    O[((size_t)b*k + r)*DIM + d] = H[((size_t)b*n + i)*DIM + d] * g;
}

// ------------------------------ readout (fused) --------------------------------
__global__ void readout_kernel(const float* __restrict__ H, int n,
                               const float* __restrict__ lw, const float* __restrict__ lb,
                               float* __restrict__ out) {
    __shared__ float ms[2*DIM];
    int b = blockIdx.x, d = threadIdx.x;
    const float* hb = H + (size_t)b*n*DIM;
    float s = 0.f;
    for (int r = 0; r < n; r++) s += hb[(size_t)r*DIM + d];
    float m = s / (float)n;
    float vs = 0.f;
    for (int r = 0; r < n; r++) { float dd = hb[(size_t)r*DIM + d] - m; vs += dd*dd; }
    ms[d]       = m;
    ms[DIM + d] = sqrtf(vs / (float)(n - 1)) + 1e-6f;
    __syncthreads();
    if (d < 128) {
        float acc = lb[d];
        for (int q = 0; q < 2*DIM; q++) acc = fmaf(ms[q], lw[q*128 + d], acc);
        out[b*128 + d] = acc;
    }
}

// ------------------------------ launch ----------------------------------------
extern "C" void kernel_launch(void* const* d_in, const int* in_sizes, int n_in,
                              void* d_out, int out_size) {
    const float* x    = (const float*)d_in[0];
    const float* adj  = (const float*)d_in[1];
    const float* pos  = (const float*)d_in[2];
    const float* in_w = (const float*)d_in[3];
    const float* in_b = (const float*)d_in[4];
    const float* pw1  = (const float*)d_in[5];
    const float* pb1  = (const float*)d_in[6];
    const float* pw2  = (const float*)d_in[7];
    const float* pb2  = (const float*)d_in[8];
    const float* bg   = (const float*)d_in[9];
    const float* bb   = (const float*)d_in[10];
    const float* bw1  = (const float*)d_in[11];
    const float* bb1  = (const float*)d_in[12];
    const float* bw2  = (const float*)d_in[13];
    const float* bb2  = (const float*)d_in[14];
    const float* beps = (const float*)d_in[15];
    const float* pp   = (const float*)d_in[16];
    const float* lw   = (const float*)d_in[17];
    const float* lb   = (const float*)d_in[18];

    float *p_h, *p_h2, *p_hn, *p_t, *p_pe;
    cudaGetSymbolAddress((void**)&p_h,  g_h);
    cudaGetSymbolAddress((void**)&p_h2, g_h2);
    cudaGetSymbolAddress((void**)&p_hn, g_hn);
    cudaGetSymbolAddress((void**)&p_t,  g_t);
    cudaGetSymbolAddress((void**)&p_pe, g_pe);

    stats_prologue_kernel<<<1, 256>>>(pos, pp);
    pos_mid_kernel<<<NODES, 256>>>(pos, pw1, pb1);                  // -> g_hn
    launch_sgemm(p_hn, pw2, pb2, nullptr, p_pe, NODES, 0);
    embed_kernel<<<BATCH*NODES, 256>>>(x, in_w, in_b);              // -> g_h
    build_csr_kernel<<<NODES/8, 256>>>(adj);

    float* curH = p_h;
    int n = NODES, adjSel = 0;
    for (int blk = 0; blk < 8; blk++) {
        int rows = BATCH*n;
        rowstats_kernel<<<rows/8, 256>>>(curH, rows);
        combine_kernel<<<rows, 256>>>(curH, n, adjSel, beps, blk,
                                      bg + blk*DIM, bb + blk*DIM);  // -> g_t
        launch_sgemm(p_t,  bw1 + blk*DIM*DIM, bb1 + blk*DIM, nullptr, p_hn, rows, 1);
        launch_sgemm(p_hn, bw2 + blk*DIM*DIM, bb2 + blk*DIM, curH,    curH, rows, 2);
        if ((blk & 1) && blk < 6) {
            int dep = blk >> 1;
            int k = n / 2;
            score_kernel<<<rows/8, 256>>>(curH, pp + dep*DIM, dep, rows);
            int newSel = (adjSel == 1) ? 2 : 1;
            topk_subadj_kernel<<<BATCH, 1024>>>(n, k, adjSel, newSel);
            float* newH = (curH == p_h) ? p_h2 : p_h;
            gather_kernel<<<BATCH*k, 256>>>(curH, newH, n, k);
            adjSel = newSel;
            curH = newH;
            n = k;
        }
    }

    readout_kernel<<<BATCH, 256>>>(curH, n, lw, lb, (float*)d_out);
}

// round 9
// speedup vs baseline: 1.0018x; 1.0018x over previous
#include <cuda_runtime.h>
#include <math.h>

#define DIM     256
#define BATCH   4
#define NODES   2048
#define MAXDEG  64
#define POOLMAX 1024
#define STOT    (BATCH*NODES)   // stats stride (max rows)

// ---------------- persistent device scratch -----------------------------------
__device__ float  g_h [BATCH*NODES*DIM];
__device__ float  g_h2[BATCH*NODES*DIM];
__device__ float  g_hn[BATCH*NODES*DIM];
__device__ float  g_t [BATCH*NODES*DIM];
__device__ float  g_pe[NODES*DIM];
__device__ float2 g_spart [4*STOT];   // per-column-tile partial (sum, sumsq)
__device__ float  g_scpart[4*STOT];   // per-column-tile partial score dot
__device__ float  g_gate [BATCH*POOLMAX];
__device__ float  g_posstat[8];
__device__ float  g_pnorm[4];
__device__ int    g_idx[BATCH*POOLMAX];
__device__ int    g_map[BATCH*NODES];
__device__ int    g_cols0[NODES*MAXDEG];
__device__ int    g_cnt0 [NODES];
__device__ int    g_colsA[BATCH*POOLMAX*MAXDEG];
__device__ int    g_cntA [BATCH*POOLMAX];
__device__ int    g_colsB[BATCH*POOLMAX*MAXDEG];
__device__ int    g_cntB [BATCH*POOLMAX];

// ---------------- f32x2 packed-FMA helpers (sm_10x) ---------------------------
__device__ __forceinline__ unsigned long long pack2s(float x) {
    unsigned long long r;
    asm("mov.b64 %0, {%1, %1};" : "=l"(r) : "f"(x));
    return r;
}
__device__ __forceinline__ unsigned long long pack2(float x, float y) {
    unsigned long long r;
    asm("mov.b64 %0, {%1, %2};" : "=l"(r) : "f"(x), "f"(y));
    return r;
}
__device__ __forceinline__ void ffma2(unsigned long long &d, unsigned long long a,
                                      unsigned long long b) {
    asm("fma.rn.f32x2 %0, %1, %2, %3;" : "=l"(d) : "l"(a), "l"(b), "l"(d));
}
__device__ __forceinline__ void unpack2(unsigned long long v, float &lo, float &hi) {
    asm("mov.b64 {%0, %1}, %2;" : "=f"(lo), "=f"(hi) : "l"(v));
}

// ---------------------------- prologue kernels --------------------------------

__global__ void stats_prologue_kernel(const float* __restrict__ pos,
                                      const float* __restrict__ pp) {
    __shared__ float red[256];
    __shared__ float smean;
    int t = threadIdx.x;
    for (int c = 0; c < 3; c++) {
        float s = 0.f;
        for (int i = t; i < NODES; i += 256) s += pos[i*3 + c];
        red[t] = s; __syncthreads();
        for (int o = 128; o > 0; o >>= 1) { if (t < o) red[t] += red[t+o]; __syncthreads(); }
        if (t == 0) smean = red[0] / (float)NODES;
        __syncthreads();
        float m = smean;
        float ss = 0.f;
        for (int i = t; i < NODES; i += 256) { float d = pos[i*3 + c] - m; ss += d*d; }
        red[t] = ss; __syncthreads();
        for (int o = 128; o > 0; o >>= 1) { if (t < o) red[t] += red[t+o]; __syncthreads(); }
        if (t == 0) {
            float var = (float)BATCH * red[0] / (float)(BATCH*NODES - 1);
            g_posstat[c]   = m;
            g_posstat[3+c] = 1.f / (sqrtf(var) + 1e-8f);
        }
        __syncthreads();
    }
    for (int dep = 0; dep < 3; dep++) {
        float v = pp[dep*DIM + t];
        red[t] = v*v; __syncthreads();
        for (int o = 128; o > 0; o >>= 1) { if (t < o) red[t] += red[t+o]; __syncthreads(); }
        if (t == 0) g_pnorm[dep] = 1.f / sqrtf(red[0]);
        __syncthreads();
    }
}

__global__ void pos_mid_kernel(const float* __restrict__ pos,
                               const float* __restrict__ pw1,
                               const float* __restrict__ pb1) {
    int i = blockIdx.x, d = threadIdx.x;
    __shared__ float pn[3];
    if (d < 3) pn[d] = (pos[i*3 + d] - g_posstat[d]) * g_posstat[3+d];
    __syncthreads();
    float a = pb1[d] + pn[0]*pw1[d] + pn[1]*pw1[DIM + d] + pn[2]*pw1[2*DIM + d];
    g_hn[i*DIM + d] = a / (1.f + __expf(-a));
}

// h = x@in_w + in_b + pe ; also emits row stats partials (exact, part0)
__global__ void embed_kernel(const float* __restrict__ x,
                             const float* __restrict__ in_w,
                             const float* __restrict__ in_b) {
    int r = blockIdx.x, d = threadIdx.x;
    __shared__ float xr[16];
    __shared__ float w1[8], w2[8];
    if (d < 16) xr[d] = x[r*16 + d];
    __syncthreads();
    float a = in_b[d] + g_pe[(r & (NODES-1))*DIM + d];
#pragma unroll
    for (int k = 0; k < 16; k++) a += xr[k]*in_w[k*DIM + d];
    g_h[(size_t)r*DIM + d] = a;
    // block-reduce sum & sumsq
    float s1 = a, s2 = a*a;
#pragma unroll
    for (int o = 16; o; o >>= 1) {
        s1 += __shfl_xor_sync(0xffffffffu, s1, o);
        s2 += __shfl_xor_sync(0xffffffffu, s2, o);
    }
    int warp = d >> 5, lane = d & 31;
    if (lane == 0) { w1[warp] = s1; w2[warp] = s2; }
    __syncthreads();
    if (d == 0) {
        float S1 = 0.f, S2 = 0.f;
#pragma unroll
        for (int q = 0; q < 8; q++) { S1 += w1[q]; S2 += w2[q]; }
        g_spart[r] = make_float2(S1, S2);
    } else if (d < 4) {
        g_spart[d*STOT + r] = make_float2(0.f, 0.f);
    }
}

__global__ void build_csr_kernel(const float* __restrict__ adj) {
    int warp = (blockIdx.x*blockDim.x + threadIdx.x) >> 5;
    int lane = threadIdx.x & 31;
    if (warp >= NODES) return;
    int base = 0;
    for (int it = 0; it < NODES/32; it++) {
        int col = it*32 + lane;
        float v = adj[(size_t)warp*NODES + col];
        unsigned m = __ballot_sync(0xffffffffu, v > 0.f);
        if (v > 0.f) {
            int p = base + __popc(m & ((1u << lane) - 1u));
            if (p < MAXDEG) g_cols0[warp*MAXDEG + p] = col;
        }
        base += __popc(m);
    }
    if (lane == 0) g_cnt0[warp] = base < MAXDEG ? base : MAXDEG;
}

// t_i = (1+eps)*LN(h_i) + sum_j LN(h_j); (m,rstd) finalized from partials in smem
__global__ void combine_kernel(const float* __restrict__ H, int n, int adjSel,
                               const float* __restrict__ beps, int blk,
                               const float* __restrict__ gam,
                               const float* __restrict__ bet) {
    int b = blockIdx.x / n, i = blockIdx.x % n, d = threadIdx.x;
    const int* cols; const int* cnt; int rowbase;
    if (adjSel == 0)      { cols = g_cols0; cnt = g_cnt0; rowbase = i; }
    else if (adjSel == 1) { cols = g_colsA; cnt = g_cntA; rowbase = b*POOLMAX + i; }
    else                  { cols = g_colsB; cnt = g_cntB; rowbase = b*POOLMAX + i; }
    __shared__ int    cs [MAXDEG];
    __shared__ float2 sst[MAXDEG + 1];   // (m, rstd) for self + neighbors
    int c = cnt[rowbase];
    if (d < c) cs[d] = cols[rowbase*MAXDEG + d];
    __syncthreads();
    if (d <= c) {
        int j = (d == 0) ? i : cs[d-1];
        int row = b*n + j;
        float2 p0 = g_spart[row];
        float2 p1 = g_spart[STOT   + row];
        float2 p2 = g_spart[2*STOT + row];
        float2 p3 = g_spart[3*STOT + row];
        float sum = p0.x + p1.x + p2.x + p3.x;
        float sq  = p0.y + p1.y + p2.y + p3.y;
        float m   = sum * (1.f/DIM);
        float var = fmaxf(sq * (1.f/DIM) - m*m, 0.f);
        sst[d] = make_float2(m, rsqrtf(var + 1e-5f));
    }
    __syncthreads();
    float eps = beps[blk];
    float gd = gam[d], bd = bet[d];
    const float* hb = H + (size_t)b*n*DIM;
    float2 si = sst[0];
    float acc = (1.f + eps)*((hb[(size_t)i*DIM + d] - si.x)*si.y*gd + bd);
    for (int q = 0; q < c; q++) {
        float2 sj = sst[q+1];
        acc += (hb[(size_t)cs[q]*DIM + d] - sj.x)*sj.y*gd + bd;
    }
    g_t[((size_t)b*n + i)*DIM + d] = acc;
}

// ------------- SGEMM 64x64 tile, BK=16, 128 thr, 4x8/thread (f32x2) -----------
// mode 0: C=acc+bias ; 1: silu ; 2: res+acc+bias (+stats/score partials)
__global__ __launch_bounds__(128, 4)
void sgemm64(const float* __restrict__ A, const float* __restrict__ Bw,
             const float* __restrict__ bias, const float* __restrict__ res,
             float* __restrict__ C, int mode,
             const float* __restrict__ pvec, int doScore) {
    __shared__ float As[2][16][64];
    __shared__ float Bs[2][16][64];
    int t  = threadIdx.x;
    int bm = blockIdx.y, bn = blockIdx.x;
    int ty = t >> 3, tx = t & 7;
    int arow = t >> 1, acol = (t & 1)*8;
    int brow = t >> 3, bcol = (t & 7)*8;
    const float* Ap = A  + (size_t)(bm*64 + arow)*DIM + acol;
    const float* Bp = Bw + (size_t)brow*DIM + bn*64 + bcol;

    unsigned long long acc[4][4];
#pragma unroll
    for (int i = 0; i < 4; i++)
#pragma unroll
        for (int j = 0; j < 4; j++) acc[i][j] = 0ull;

    float4 av0 = *(const float4*)(Ap);
    float4 av1 = *(const float4*)(Ap + 4);
    float4 bv0 = *(const float4*)(Bp);
    float4 bv1 = *(const float4*)(Bp + 4);
    As[0][acol+0][arow] = av0.x; As[0][acol+1][arow] = av0.y;
    As[0][acol+2][arow] = av0.z; As[0][acol+3][arow] = av0.w;
    As[0][acol+4][arow] = av1.x; As[0][acol+5][arow] = av1.y;
    As[0][acol+6][arow] = av1.z; As[0][acol+7][arow] = av1.w;
    *(float4*)&Bs[0][brow][bcol]     = bv0;
    *(float4*)&Bs[0][brow][bcol + 4] = bv1;
    __syncthreads();

    int cur = 0;
    for (int k0 = 16; k0 < DIM; k0 += 16) {
        av0 = *(const float4*)(Ap + k0);
        av1 = *(const float4*)(Ap + k0 + 4);
        bv0 = *(const float4*)(Bp + (size_t)k0*DIM);
        bv1 = *(const float4*)(Bp + (size_t)k0*DIM + 4);
#pragma unroll
        for (int kk = 0; kk < 16; kk++) {
            float4 a4 = *(const float4*)&As[cur][kk][ty*4];
            float4 bA = *(const float4*)&Bs[cur][kk][tx*8];
            float4 bB = *(const float4*)&Bs[cur][kk][tx*8 + 4];
            unsigned long long bp[4] = { pack2(bA.x, bA.y), pack2(bA.z, bA.w),
                                         pack2(bB.x, bB.y), pack2(bB.z, bB.w) };
            float am[4] = { a4.x, a4.y, a4.z, a4.w };
#pragma unroll
            for (int i = 0; i < 4; i++) {
                unsigned long long ap = pack2s(am[i]);
#pragma unroll
                for (int j = 0; j < 4; j++) ffma2(acc[i][j], ap, bp[j]);
            }
        }
        int nxt = cur ^ 1;
        As[nxt][acol+0][arow] = av0.x; As[nxt][acol+1][arow] = av0.y;
        As[nxt][acol+2][arow] = av0.z; As[nxt][acol+3][arow] = av0.w;
        As[nxt][acol+4][arow] = av1.x; As[nxt][acol+5][arow] = av1.y;
        As[nxt][acol+6][arow] = av1.z; As[nxt][acol+7][arow] = av1.w;
        *(float4*)&Bs[nxt][brow][bcol]     = bv0;
        *(float4*)&Bs[nxt][brow][bcol + 4] = bv1;
        __syncthreads();
        cur = nxt;
    }
#pragma unroll
    for (int kk = 0; kk < 16; kk++) {
        float4 a4 = *(const float4*)&As[cur][kk][ty*4];
        float4 bA = *(const float4*)&Bs[cur][kk][tx*8];
        float4 bB = *(const float4*)&Bs[cur][kk][tx*8 + 4];
        unsigned long long bp[4] = { pack2(bA.x, bA.y), pack2(bA.z, bA.w),
                                     pack2(bB.x, bB.y), pack2(bB.z, bB.w) };
        float am[4] = { a4.x, a4.y, a4.z, a4.w };
#pragma unroll
        for (int i = 0; i < 4; i++) {
            unsigned long long ap = pack2s(am[i]);
#pragma unroll
            for (int j = 0; j < 4; j++) ffma2(acc[i][j], ap, bp[j]);
        }
    }

#pragma unroll
    for (int i = 0; i < 4; i++) {
        int rg = bm*64 + ty*4 + i;
        float rsum = 0.f, rsq = 0.f, rsc = 0.f;
#pragma unroll
        for (int j = 0; j < 4; j++) {
            int cg = bn*64 + tx*8 + j*2;
            float lo, hi;
            unpack2(acc[i][j], lo, hi);
            float v0 = lo + bias[cg];
            float v1 = hi + bias[cg + 1];
            if (mode == 1) {
                v0 = v0 / (1.f + __expf(-v0));
                v1 = v1 / (1.f + __expf(-v1));
            } else if (mode == 2) {
                v0 = res[(size_t)rg*DIM + cg]     + v0;
                v1 = res[(size_t)rg*DIM + cg + 1] + v1;
                rsum += v0 + v1;
                rsq  += v0*v0 + v1*v1;
                if (doScore) rsc += v0*pvec[cg] + v1*pvec[cg + 1];
            }
            C[(size_t)rg*DIM + cg]     = v0;
            C[(size_t)rg*DIM + cg + 1] = v1;
        }
        if (mode == 2) {
#pragma unroll
            for (int o = 1; o < 8; o <<= 1) {
                rsum += __shfl_xor_sync(0xffffffffu, rsum, o);
                rsq  += __shfl_xor_sync(0xffffffffu, rsq,  o);
                rsc  += __shfl_xor_sync(0xffffffffu, rsc,  o);
            }
            if (tx == 0) {
                g_spart[bn*STOT + rg] = make_float2(rsum, rsq);
                if (doScore) g_scpart[bn*STOT + rg] = rsc;
            }
        }
    }
}

// ------------- SGEMM 32x64 tile, BK=16, 128 thr, 2x8/thread (f32x2) ------------
__global__ __launch_bounds__(128, 8)
void sgemm32(const float* __restrict__ A, const float* __restrict__ Bw,
             const float* __restrict__ bias, const float* __restrict__ res,
             float* __restrict__ C, int mode,
             const float* __restrict__ pvec, int doScore) {
    __shared__ float As[2][16][32];
    __shared__ float Bs[2][16][64];
    int t  = threadIdx.x;
    int bm = blockIdx.y, bn = blockIdx.x;
    int ty = t >> 3, tx = t & 7;
    int arow = t >> 2, acol = (t & 3)*4;
    int brow = t >> 3, bcol = (t & 7)*8;
    const float* Ap = A  + (size_t)(bm*32 + arow)*DIM + acol;
    const float* Bp = Bw + (size_t)brow*DIM + bn*64 + bcol;

    unsigned long long acc[2][4];
#pragma unroll
    for (int i = 0; i < 2; i++)
#pragma unroll
        for (int j = 0; j < 4; j++) acc[i][j] = 0ull;

    float4 av = *(const float4*)(Ap);
    float4 b0 = *(const float4*)(Bp);
    float4 b1 = *(const float4*)(Bp + 4);
    As[0][acol+0][arow] = av.x; As[0][acol+1][arow] = av.y;
    As[0][acol+2][arow] = av.z; As[0][acol+3][arow] = av.w;
    *(float4*)&Bs[0][brow][bcol]     = b0;
    *(float4*)&Bs[0][brow][bcol + 4] = b1;
    __syncthreads();

    int cur = 0;
    for (int k0 = 16; k0 < DIM; k0 += 16) {
        av = *(const float4*)(Ap + k0);
        b0 = *(const float4*)(Bp + (size_t)k0*DIM);
        b1 = *(const float4*)(Bp + (size_t)k0*DIM + 4);
#pragma unroll
        for (int kk = 0; kk < 16; kk++) {
            float2 a2 = *(const float2*)&As[cur][kk][ty*2];
            float4 bA = *(const float4*)&Bs[cur][kk][tx*8];
            float4 bB = *(const float4*)&Bs[cur][kk][tx*8 + 4];
            unsigned long long bp[4] = { pack2(bA.x, bA.y), pack2(bA.z, bA.w),
                                         pack2(bB.x, bB.y), pack2(bB.z, bB.w) };
            unsigned long long ap0 = pack2s(a2.x), ap1 = pack2s(a2.y);
#pragma unroll
            for (int j = 0; j < 4; j++) { ffma2(acc[0][j], ap0, bp[j]); ffma2(acc[1][j], ap1, bp[j]); }
        }
        int nxt = cur ^ 1;
        As[nxt][acol+0][arow] = av.x; As[nxt][acol+1][arow] = av.y;
        As[nxt][acol+2][arow] = av.z; As[nxt][acol+3][arow] = av.w;
        *(float4*)&Bs[nxt][brow][bcol]     = b0;
        *(float4*)&Bs[nxt][brow][bcol + 4] = b1;
        __syncthreads();
        cur = nxt;
    }
#pragma unroll
    for (int kk = 0; kk < 16; kk++) {
        float2 a2 = *(const float2*)&As[cur][kk][ty*2];
        float4 bA = *(const float4*)&Bs[cur][kk][tx*8];
        float4 bB = *(const float4*)&Bs[cur][kk][tx*8 + 4];
        unsigned long long bp[4] = { pack2(bA.x, bA.y), pack2(bA.z, bA.w),
                                     pack2(bB.x, bB.y), pack2(bB.z, bB.w) };
        unsigned long long ap0 = pack2s(a2.x), ap1 = pack2s(a2.y);
#pragma unroll
        for (int j = 0; j < 4; j++) { ffma2(acc[0][j], ap0, bp[j]); ffma2(acc[1][j], ap1, bp[j]); }
    }

#pragma unroll
    for (int i = 0; i < 2; i++) {
        int rg = bm*32 + ty*2 + i;
        float rsum = 0.f, rsq = 0.f, rsc = 0.f;
#pragma unroll
        for (int j = 0; j < 4; j++) {
            int cg = bn*64 + tx*8 + j*2;
            float lo, hi;
            unpack2(acc[i][j], lo, hi);
            float v0 = lo + bias[cg];
            float v1 = hi + bias[cg + 1];
            if (mode == 1) {
                v0 = v0 / (1.f + __expf(-v0));
                v1 = v1 / (1.f + __expf(-v1));
            } else if (mode == 2) {
                v0 = res[(size_t)rg*DIM + cg]     + v0;
                v1 = res[(size_t)rg*DIM + cg + 1] + v1;
                rsum += v0 + v1;
                rsq  += v0*v0 + v1*v1;
                if (doScore) rsc += v0*pvec[cg] + v1*pvec[cg + 1];
            }
            C[(size_t)rg*DIM + cg]     = v0;
            C[(size_t)rg*DIM + cg + 1] = v1;
        }
        if (mode == 2) {
#pragma unroll
            for (int o = 1; o < 8; o <<= 1) {
                rsum += __shfl_xor_sync(0xffffffffu, rsum, o);
                rsq  += __shfl_xor_sync(0xffffffffu, rsq,  o);
                rsc  += __shfl_xor_sync(0xffffffffu, rsc,  o);
            }
            if (tx == 0) {
                g_spart[bn*STOT + rg] = make_float2(rsum, rsq);
                if (doScore) g_scpart[bn*STOT + rg] = rsc;
            }
        }
    }
}

static inline void launch_sgemm(const float* A, const float* Bw, const float* bias,
                                const float* res, float* C, int rows, int mode,
                                const float* pvec, int doScore) {
    if (rows >= 4096) sgemm64<<<dim3(4, rows/64), 128>>>(A, Bw, bias, res, C, mode, pvec, doScore);
    else              sgemm32<<<dim3(4, rows/32), 128>>>(A, Bw, bias, res, C, mode, pvec, doScore);
}

// ------------------------------ pooling ---------------------------------------
// exact top-k (lax.top_k tie-break) + compaction + sub-adjacency
__global__ void topk_subadj_kernel(int n, int k, int dep, int oldSel, int newSel) {
    __shared__ float s[NODES];
    __shared__ unsigned char sel[NODES];
    int b = blockIdx.x, t = threadIdx.x, bd = blockDim.x;
    float pn = g_pnorm[dep];
    for (int i = t; i < n; i += bd) {
        int row = b*n + i;
        s[i] = (g_scpart[row] + g_scpart[STOT + row] +
                g_scpart[2*STOT + row] + g_scpart[3*STOT + row]) * pn;
    }
    __syncthreads();
    for (int i = t; i < n; i += bd) {
        float si = s[i]; int r = 0;
        for (int j = 0; j < n; j++) {
            float sj = s[j];
            r += (sj > si) || (sj == si && j < i);
        }
        sel[i] = (r < k) ? 1 : 0;
    }
    __syncthreads();
    for (int i = t; i < n; i += bd) {
        if (sel[i]) {
            int p = 0;
            for (int j = 0; j < i; j++) p += sel[j];
            g_idx [b*POOLMAX + p] = i;
            g_gate[b*POOLMAX + p] = tanhf(s[i]);
            g_map [b*NODES + i]   = p;
        } else {
            g_map[b*NODES + i] = -1;
        }
    }
    __syncthreads();
    for (int r = t; r < k; r += bd) {
        int i = g_idx[b*POOLMAX + r];
        const int* ocols; const int* ocnt; int obase;
        if (oldSel == 0)      { ocols = g_cols0; ocnt = g_cnt0; obase = i; }
        else if (oldSel == 1) { ocols = g_colsA; ocnt = g_cntA; obase = b*POOLMAX + i; }
        else                  { ocols = g_colsB; ocnt = g_cntB; obase = b*POOLMAX + i; }
        int* ncols = (newSel == 1) ? g_colsA : g_colsB;
        int* ncnt  = (newSel == 1) ? g_cntA  : g_cntB;
        int c = ocnt[obase], w = 0, nb = b*POOLMAX + r;
        for (int q = 0; q < c; q++) {
            int j  = ocols[obase*MAXDEG + q];
            int nj = g_map[b*NODES + j];
            if (nj >= 0) ncols[nb*MAXDEG + w++] = nj;
        }
        ncnt[nb] = w;
    }
}

// gather rows with gate; emits exact stats (part0) for next block's LN
__global__ void gather_kernel(const float* __restrict__ H, float* __restrict__ O,
                              int n, int k) {
    __shared__ float w1[8], w2[8];
    int b = blockIdx.x / k, r = blockIdx.x % k, d = threadIdx.x;
    int i  = g_idx [b*POOLMAX + r];
    float g = g_gate[b*POOLMAX + r];
    float v = H[((size_t)b*n + i)*DIM + d] * g;
    int orow = b*k + r;
    O[(size_t)orow*DIM + d] = v;
    float s1 = v, s2 = v*v;
#pragma unroll
    for (int o = 16; o; o >>= 1) {
        s1 += __shfl_xor_sync(0xffffffffu, s1, o);
        s2 += __shfl_xor_sync(0xffffffffu, s2, o);
    }
    int warp = d >> 5, lane = d & 31;
    if (lane == 0) { w1[warp] = s1; w2[warp] = s2; }
    __syncthreads();
    if (d == 0) {
        float S1 = 0.f, S2 = 0.f;
#pragma unroll
        for (int q = 0; q < 8; q++) { S1 += w1[q]; S2 += w2[q]; }
        g_spart[orow] = make_float2(S1, S2);
    } else if (d < 4) {
        g_spart[d*STOT + orow] = make_float2(0.f, 0.f);
    }
}

// -------------------- readout: parallel single-pass mean/std + GEMV -----------
// 1024 threads = 256 dims x 4 row-chunks; var = (S2 - S1*m)/(n-1)
__global__ void readout_kernel(const float* __restrict__ H, int n,
                               const float* __restrict__ lw, const float* __restrict__ lb,
                               float* __restrict__ out) {
    __shared__ float ps1[4*DIM];
    __shared__ float ps2[4*DIM];
    __shared__ float ms[2*DIM];
    int b = blockIdx.x, t = threadIdx.x;
    int d = t & (DIM-1), chunk = t >> 8;        // 4 chunks of n/4 rows
    int rpc = n >> 2;
    const float* hb = H + (size_t)b*n*DIM;
    float s1 = 0.f, s2 = 0.f;
    for (int r = chunk*rpc; r < (chunk+1)*rpc; r++) {
        float v = hb[(size_t)r*DIM + d];
        s1 += v; s2 += v*v;
    }
    ps1[chunk*DIM + d] = s1;
    ps2[chunk*DIM + d] = s2;
    __syncthreads();
    if (t < DIM) {
        float S1 = ps1[d] + ps1[DIM + d] + ps1[2*DIM + d] + ps1[3*DIM + d];
        float S2 = ps2[d] + ps2[DIM + d] + ps2[2*DIM + d] + ps2[3*DIM + d];
        float m  = S1 / (float)n;
        float var = fmaxf((S2 - S1*m) / (float)(n - 1), 0.f);
        ms[d]       = m;
        ms[DIM + d] = sqrtf(var) + 1e-6f;
    }
    __syncthreads();
    if (t < 128) {
        float acc = lb[t];
        for (int q = 0; q < 2*DIM; q++) acc = fmaf(ms[q], lw[q*128 + t], acc);
        out[b*128 + t] = acc;
    }
}

// ------------------------------ launch ----------------------------------------
extern "C" void kernel_launch(void* const* d_in, const int* in_sizes, int n_in,
                              void* d_out, int out_size) {
    const float* x    = (const float*)d_in[0];
    const float* adj  = (const float*)d_in[1];
    const float* pos  = (const float*)d_in[2];
    const float* in_w = (const float*)d_in[3];
    const float* in_b = (const float*)d_in[4];
    const float* pw1  = (const float*)d_in[5];
    const float* pb1  = (const float*)d_in[6];
    const float* pw2  = (const float*)d_in[7];
    const float* pb2  = (const float*)d_in[8];
    const float* bg   = (const float*)d_in[9];
    const float* bb   = (const float*)d_in[10];
    const float* bw1  = (const float*)d_in[11];
    const float* bb1  = (const float*)d_in[12];
    const float* bw2  = (const float*)d_in[13];
    const float* bb2  = (const float*)d_in[14];
    const float* beps = (const float*)d_in[15];
    const float* pp   = (const float*)d_in[16];
    const float* lw   = (const float*)d_in[17];
    const float* lb   = (const float*)d_in[18];

    float *p_h, *p_h2, *p_hn, *p_t, *p_pe;
    cudaGetSymbolAddress((void**)&p_h,  g_h);
    cudaGetSymbolAddress((void**)&p_h2, g_h2);
    cudaGetSymbolAddress((void**)&p_hn, g_hn);
    cudaGetSymbolAddress((void**)&p_t,  g_t);
    cudaGetSymbolAddress((void**)&p_pe, g_pe);

    stats_prologue_kernel<<<1, 256>>>(pos, pp);
    pos_mid_kernel<<<NODES, 256>>>(pos, pw1, pb1);                  // -> g_hn
    launch_sgemm(p_hn, pw2, pb2, nullptr, p_pe, NODES, 0, nullptr, 0);
    embed_kernel<<<BATCH*NODES, 256>>>(x, in_w, in_b);              // -> g_h + stats
    build_csr_kernel<<<NODES/8, 256>>>(adj);

    float* curH = p_h;
    int n = NODES, adjSel = 0;
    for (int blk = 0; blk < 8; blk++) {
        int rows = BATCH*n;
        int pool = ((blk & 1) && blk < 6);
        int dep  = blk >> 1;
        combine_kernel<<<rows, 256>>>(curH, n, adjSel, beps, blk,
                                      bg + blk*DIM, bb + blk*DIM);  // -> g_t
        launch_sgemm(p_t,  bw1 + blk*DIM*DIM, bb1 + blk*DIM, nullptr, p_hn, rows, 1,
                     nullptr, 0);
        launch_sgemm(p_hn, bw2 + blk*DIM*DIM, bb2 + blk*DIM, curH,    curH, rows, 2,
                     pp + dep*DIM, pool);
        if (pool) {
            int k = n / 2;
            int newSel = (adjSel == 1) ? 2 : 1;
            topk_subadj_kernel<<<BATCH, 1024>>>(n, k, dep, adjSel, newSel);
            float* newH = (curH == p_h) ? p_h2 : p_h;
            gather_kernel<<<BATCH*k, 256>>>(curH, newH, n, k);
            adjSel = newSel;
            curH = newH;
            n = k;
        }
    }

    readout_kernel<<<BATCH, 1024>>>(curH, n, lw, lb, (float*)d_out);
}